// round 2
// baseline (speedup 1.0000x reference)
#include <cuda_runtime.h>
#include <cstdint>

#define Bdim 4
#define Hdim 512
#define Wdim 512
#define C_TOTAL 25
#define CS (Hdim * Wdim)

typedef unsigned long long u64;

__device__ __forceinline__ void fma2(u64& d, u64 a, u64 b) {
    asm("fma.rn.f32x2 %0, %1, %2, %0;" : "+l"(d) : "l"(a), "l"(b));
}
__device__ __forceinline__ u64 dup2(float v) {
    u64 r; asm("mov.b64 %0, {%1, %1};" : "=l"(r) : "f"(v)); return r;
}
__device__ __forceinline__ u64 pack2(float lo, float hi) {
    u64 r; asm("mov.b64 %0, {%1, %2};" : "=l"(r) : "f"(lo), "f"(hi)); return r;
}
__device__ __forceinline__ void unpack2(u64 v, float& lo, float& hi) {
    asm("mov.b64 {%0, %1}, %2;" : "=f"(lo), "=f"(hi) : "l"(v));
}
__device__ __forceinline__ uint32_t smaddr(const void* p) {
    return (uint32_t)__cvta_generic_to_shared(p);
}
__device__ __forceinline__ void cp16(uint32_t dst, const float* src) {
    asm volatile("cp.async.ca.shared.global [%0], [%1], 16;" :: "r"(dst), "l"(src));
}
__device__ __forceinline__ void cp4(uint32_t dst, const float* src) {
    asm volatile("cp.async.ca.shared.global [%0], [%1], 4;" :: "r"(dst), "l"(src));
}
__device__ __forceinline__ void cpcommit() { asm volatile("cp.async.commit_group;"); }
template<int N> __device__ __forceinline__ void cpwait() {
    asm volatile("cp.async.wait_group %0;" :: "n"(N));
}

// Shared-memory tiled dilated 3x3 conv layer.
// Block computes a TH x 64 output tile for the 2 new channels (packed f32x2).
// Per input channel: cp.async the (TH+2D)x(64+2D4) input patch (reflect applied
// during fill) into a double-buffered smem tile, then row-stationary accumulate.
template<int N_IN, int D, int R, int NROWG>
__global__ void conv_layer(const float* __restrict__ g, float* __restrict__ outg,
                           const float* __restrict__ wgt, const float* __restrict__ bias2p)
{
    constexpr int TW = 64;
    constexpr int TH = R * NROWG;                 // 64
    constexpr int D4 = (D + 3) & ~3;              // col halo rounded to float4
    constexpr int TCW = TW + 2 * D4;
    constexpr int TROWS = TH + 2 * D;
    constexpr int NT = TW * NROWG;                // threads per block
    constexpr int TS = TROWS * TCW;

    extern __shared__ char smraw[];
    u64* ws2 = (u64*)smraw;
    float* tile0 = (float*)(smraw + ((N_IN * 9 * 8 + 15) & ~15));
    float* tile1 = tile0 + TS;

    const int tid = threadIdx.x;
    const int bx = blockIdx.x, by = blockIdx.y, b = blockIdx.z;
    const int c0 = bx * TW, r0 = by * TH;
    const int gr0 = r0 - D, gc0 = c0 - D4;

    for (int i = tid; i < N_IN * 9; i += NT)
        ws2[i] = pack2(wgt[i], wgt[N_IN * 9 + i]);   // pack (oc0, oc1) weights

    const u64 bias2 = pack2(bias2p[0], bias2p[1]);

    auto fill = [&](int ic, float* dstbuf) {
        const float* plane = g + ((size_t)(b * C_TOTAL + ic)) * CS;
        uint32_t dbase = smaddr(dstbuf);
        #pragma unroll 1
        for (int idx = tid; idx < TROWS * (TCW / 4); idx += NT) {
            int tr = idx / (TCW / 4);
            int cc = idx - tr * (TCW / 4);
            int gr = gr0 + tr;
            if (gr < 0) gr = -gr; else if (gr >= Hdim) gr = 2 * Hdim - 2 - gr;
            int gc = gc0 + cc * 4;
            uint32_t dst = dbase + (uint32_t)(tr * TCW + cc * 4) * 4u;
            const float* srow = plane + (size_t)gr * Wdim;
            if (gc >= 0 && gc + 4 <= Wdim) {
                cp16(dst, srow + gc);
            } else {
                #pragma unroll
                for (int k = 0; k < 4; ++k) {
                    int c = gc + k;
                    if (c < 0) c = -c; else if (c >= Wdim) c = 2 * Wdim - 2 - c;
                    cp4(dst + 4u * k, srow + c);
                }
            }
        }
    };

    const int col  = tid & (TW - 1);
    const int rowg = tid / TW;

    u64 acc[R];
    #pragma unroll
    for (int m = 0; m < R; ++m) acc[m] = bias2;

    fill(0, tile0); cpcommit();

    #pragma unroll 1
    for (int ic = 0; ic < N_IN; ++ic) {
        if (ic + 1 < N_IN) {
            fill(ic + 1, ((ic + 1) & 1) ? tile1 : tile0);
            cpcommit();
            cpwait<1>();           // current channel's fill complete (per-thread)
        } else {
            cpwait<0>();
        }
        __syncthreads();           // fill visible block-wide (also covers ws2 on ic=0)

        const u64* wrow = ws2 + ic * 9;
        u64 w00 = wrow[0], w01 = wrow[1], w02 = wrow[2];
        u64 w10 = wrow[3], w11 = wrow[4], w12 = wrow[5];
        u64 w20 = wrow[6], w21 = wrow[7], w22 = wrow[8];

        const float* base = ((ic & 1) ? tile1 : tile0) + (size_t)(rowg * R) * TCW + (D4 + col);
        #pragma unroll
        for (int j = 0; j < R + 2 * D; ++j) {
            const float* rp = base + j * TCW;
            u64 vl = dup2(rp[-D]);
            u64 vc = dup2(rp[0]);
            u64 vr = dup2(rp[D]);
            // input row feeds acc row m = j - kh*D with weight row kh
            if (j < R)                 { fma2(acc[j],       w00, vl); fma2(acc[j],       w01, vc); fma2(acc[j],       w02, vr); }
            if (j >= D && j < R + D)   { fma2(acc[j - D],   w10, vl); fma2(acc[j - D],   w11, vc); fma2(acc[j - D],   w12, vr); }
            if (j >= 2 * D)            { fma2(acc[j - 2*D], w20, vl); fma2(acc[j - 2*D], w21, vc); fma2(acc[j - 2*D], w22, vr); }
        }
        __syncthreads();           // done reading this buffer before next fill reuses it
    }

    float* o0 = outg + ((size_t)(b * C_TOTAL + N_IN)) * CS
                     + (size_t)(r0 + rowg * R) * Wdim + (c0 + col);
    #pragma unroll
    for (int m = 0; m < R; ++m) {
        float lo, hi; unpack2(acc[m], lo, hi);
        o0[(size_t)m * Wdim]      = fmaxf(lo, 0.f);
        o0[CS + (size_t)m * Wdim] = fmaxf(hi, 0.f);
    }
}

__global__ void copy_in_kernel(const float4* __restrict__ x, float4* __restrict__ out) {
    int idx = blockIdx.x * blockDim.x + threadIdx.x;
    const int P4 = CS / 4;
    if (idx >= Bdim * P4) return;
    int b = idx / P4;
    int p = idx - b * P4;
    out[(size_t)b * (C_TOTAL * P4) + p] = x[idx];
}

template<int N_IN, int D, int R, int NROWG>
static void launch_layer(float* out, const float* w, const float* bias, int layer) {
    constexpr int TW = 64, TH = R * NROWG;
    constexpr int D4 = (D + 3) & ~3;
    constexpr int TCW = TW + 2 * D4;
    constexpr int TROWS = TH + 2 * D;
    constexpr int SMEM = ((N_IN * 9 * 8 + 15) & ~15) + 2 * TROWS * TCW * 4;
    constexpr int NT = TW * NROWG;
    cudaFuncSetAttribute(conv_layer<N_IN, D, R, NROWG>,
                         cudaFuncAttributeMaxDynamicSharedMemorySize, SMEM);
    conv_layer<N_IN, D, R, NROWG>
        <<<dim3(Wdim / TW, Hdim / TH, Bdim), NT, SMEM>>>(out, out, w, bias + 2 * layer);
}

extern "C" void kernel_launch(void* const* d_in, const int* in_sizes, int n_in,
                              void* d_out, int out_size) {
    const float* x    = (const float*)d_in[0];
    const float* bias = (const float*)d_in[1];
    float* out = (float*)d_out;

    {
        int total4 = Bdim * CS / 4;
        copy_in_kernel<<<(total4 + 255) / 256, 256>>>((const float4*)x, (float4*)out);
    }

    // D<=4: R=16, 256 threads (4 row groups). D>=5: R=32, 128 threads (2 row groups).
    launch_layer< 1,  1, 16, 4>(out, (const float*)d_in[2],  bias, 0);
    launch_layer< 3,  2, 16, 4>(out, (const float*)d_in[3],  bias, 1);
    launch_layer< 5,  3, 16, 4>(out, (const float*)d_in[4],  bias, 2);
    launch_layer< 7,  4, 16, 4>(out, (const float*)d_in[5],  bias, 3);
    launch_layer< 9,  5, 32, 2>(out, (const float*)d_in[6],  bias, 4);
    launch_layer<11,  6, 32, 2>(out, (const float*)d_in[7],  bias, 5);
    launch_layer<13,  7, 32, 2>(out, (const float*)d_in[8],  bias, 6);
    launch_layer<15,  8, 32, 2>(out, (const float*)d_in[9],  bias, 7);
    launch_layer<17,  9, 32, 2>(out, (const float*)d_in[10], bias, 8);
    launch_layer<19, 10, 32, 2>(out, (const float*)d_in[11], bias, 9);
    launch_layer<21, 11, 32, 2>(out, (const float*)d_in[12], bias, 10);
    launch_layer<23, 12, 32, 2>(out, (const float*)d_in[13], bias, 11);
}

// round 3
// speedup vs baseline: 1.0019x; 1.0019x over previous
#include <cuda_runtime.h>
#include <cstdint>

#define Bdim 4
#define Hdim 512
#define Wdim 512
#define C_TOTAL 25
#define CS (Hdim * Wdim)

typedef unsigned long long u64;

__device__ __forceinline__ void fma2(u64& d, u64 a, u64 b) {
    asm("fma.rn.f32x2 %0, %1, %2, %0;" : "+l"(d) : "l"(a), "l"(b));
}
__device__ __forceinline__ u64 dup2(float v) {
    u64 r; asm("mov.b64 %0, {%1, %1};" : "=l"(r) : "f"(v)); return r;
}
__device__ __forceinline__ u64 pack2(float lo, float hi) {
    u64 r; asm("mov.b64 %0, {%1, %2};" : "=l"(r) : "f"(lo), "f"(hi)); return r;
}
__device__ __forceinline__ void unpack2(u64 v, float& lo, float& hi) {
    asm("mov.b64 {%0, %1}, %2;" : "=f"(lo), "=f"(hi) : "l"(v));
}
__device__ __forceinline__ uint32_t smaddr(const void* p) {
    return (uint32_t)__cvta_generic_to_shared(p);
}
__device__ __forceinline__ void cp16(uint32_t dst, const float* src) {
    asm volatile("cp.async.ca.shared.global [%0], [%1], 16;" :: "r"(dst), "l"(src));
}
__device__ __forceinline__ void cp4(uint32_t dst, const float* src) {
    asm volatile("cp.async.ca.shared.global [%0], [%1], 4;" :: "r"(dst), "l"(src));
}
__device__ __forceinline__ void cpcommit() { asm volatile("cp.async.commit_group;"); }
template<int N> __device__ __forceinline__ void cpwait() {
    asm volatile("cp.async.wait_group %0;" :: "n"(N));
}

// Shared-memory tiled dilated 3x3 conv layer.
// Block computes a TH x 64 output tile for the 2 new channels (packed f32x2).
// Per input channel: cp.async the (TH+2D)x(64+2D4) input patch (reflect applied
// during fill) into a double-buffered smem tile, then row-stationary accumulate.
template<int N_IN, int D, int R, int NROWG>
__global__ void conv_layer(const float* __restrict__ g, float* __restrict__ outg,
                           const float* __restrict__ wgt, const float* __restrict__ bias2p)
{
    constexpr int TW = 64;
    constexpr int TH = R * NROWG;                 // 64
    constexpr int D4 = (D + 3) & ~3;              // col halo rounded to float4
    constexpr int TCW = TW + 2 * D4;
    constexpr int TROWS = TH + 2 * D;
    constexpr int NT = TW * NROWG;                // threads per block
    constexpr int TS = TROWS * TCW;

    extern __shared__ char smraw[];
    u64* ws2 = (u64*)smraw;
    float* tile0 = (float*)(smraw + ((N_IN * 9 * 8 + 15) & ~15));
    float* tile1 = tile0 + TS;

    const int tid = threadIdx.x;
    const int bx = blockIdx.x, by = blockIdx.y, b = blockIdx.z;
    const int c0 = bx * TW, r0 = by * TH;
    const int gr0 = r0 - D, gc0 = c0 - D4;

    for (int i = tid; i < N_IN * 9; i += NT)
        ws2[i] = pack2(wgt[i], wgt[N_IN * 9 + i]);   // pack (oc0, oc1) weights

    const u64 bias2 = pack2(bias2p[0], bias2p[1]);

    auto fill = [&](int ic, float* dstbuf) {
        const float* plane = g + ((size_t)(b * C_TOTAL + ic)) * CS;
        uint32_t dbase = smaddr(dstbuf);
        #pragma unroll 1
        for (int idx = tid; idx < TROWS * (TCW / 4); idx += NT) {
            int tr = idx / (TCW / 4);
            int cc = idx - tr * (TCW / 4);
            int gr = gr0 + tr;
            if (gr < 0) gr = -gr; else if (gr >= Hdim) gr = 2 * Hdim - 2 - gr;
            int gc = gc0 + cc * 4;
            uint32_t dst = dbase + (uint32_t)(tr * TCW + cc * 4) * 4u;
            const float* srow = plane + (size_t)gr * Wdim;
            if (gc >= 0 && gc + 4 <= Wdim) {
                cp16(dst, srow + gc);
            } else {
                #pragma unroll
                for (int k = 0; k < 4; ++k) {
                    int c = gc + k;
                    if (c < 0) c = -c; else if (c >= Wdim) c = 2 * Wdim - 2 - c;
                    cp4(dst + 4u * k, srow + c);
                }
            }
        }
    };

    const int col  = tid & (TW - 1);
    const int rowg = tid / TW;

    u64 acc[R];
    #pragma unroll
    for (int m = 0; m < R; ++m) acc[m] = bias2;

    fill(0, tile0); cpcommit();

    #pragma unroll 1
    for (int ic = 0; ic < N_IN; ++ic) {
        if (ic + 1 < N_IN) {
            fill(ic + 1, ((ic + 1) & 1) ? tile1 : tile0);
            cpcommit();
            cpwait<1>();           // current channel's fill complete (per-thread)
        } else {
            cpwait<0>();
        }
        __syncthreads();           // fill visible block-wide (also covers ws2 on ic=0)

        const u64* wrow = ws2 + ic * 9;
        u64 w00 = wrow[0], w01 = wrow[1], w02 = wrow[2];
        u64 w10 = wrow[3], w11 = wrow[4], w12 = wrow[5];
        u64 w20 = wrow[6], w21 = wrow[7], w22 = wrow[8];

        const float* base = ((ic & 1) ? tile1 : tile0) + (size_t)(rowg * R) * TCW + (D4 + col);
        #pragma unroll
        for (int j = 0; j < R + 2 * D; ++j) {
            const float* rp = base + j * TCW;
            u64 vl = dup2(rp[-D]);
            u64 vc = dup2(rp[0]);
            u64 vr = dup2(rp[D]);
            // input row feeds acc row m = j - kh*D with weight row kh
            if (j < R)                 { fma2(acc[j],       w00, vl); fma2(acc[j],       w01, vc); fma2(acc[j],       w02, vr); }
            if (j >= D && j < R + D)   { fma2(acc[j - D],   w10, vl); fma2(acc[j - D],   w11, vc); fma2(acc[j - D],   w12, vr); }
            if (j >= 2 * D)            { fma2(acc[j - 2*D], w20, vl); fma2(acc[j - 2*D], w21, vc); fma2(acc[j - 2*D], w22, vr); }
        }
        __syncthreads();           // done reading this buffer before next fill reuses it
    }

    float* o0 = outg + ((size_t)(b * C_TOTAL + N_IN)) * CS
                     + (size_t)(r0 + rowg * R) * Wdim + (c0 + col);
    #pragma unroll
    for (int m = 0; m < R; ++m) {
        float lo, hi; unpack2(acc[m], lo, hi);
        o0[(size_t)m * Wdim]      = fmaxf(lo, 0.f);
        o0[CS + (size_t)m * Wdim] = fmaxf(hi, 0.f);
    }
}

__global__ void copy_in_kernel(const float4* __restrict__ x, float4* __restrict__ out) {
    int idx = blockIdx.x * blockDim.x + threadIdx.x;
    const int P4 = CS / 4;
    if (idx >= Bdim * P4) return;
    int b = idx / P4;
    int p = idx - b * P4;
    out[(size_t)b * (C_TOTAL * P4) + p] = x[idx];
}

template<int N_IN, int D, int R, int NROWG>
static void launch_layer(float* out, const float* w, const float* bias, int layer) {
    constexpr int TW = 64, TH = R * NROWG;
    constexpr int D4 = (D + 3) & ~3;
    constexpr int TCW = TW + 2 * D4;
    constexpr int TROWS = TH + 2 * D;
    constexpr int SMEM = ((N_IN * 9 * 8 + 15) & ~15) + 2 * TROWS * TCW * 4;
    constexpr int NT = TW * NROWG;
    cudaFuncSetAttribute(conv_layer<N_IN, D, R, NROWG>,
                         cudaFuncAttributeMaxDynamicSharedMemorySize, SMEM);
    conv_layer<N_IN, D, R, NROWG>
        <<<dim3(Wdim / TW, Hdim / TH, Bdim), NT, SMEM>>>(out, out, w, bias + 2 * layer);
}

extern "C" void kernel_launch(void* const* d_in, const int* in_sizes, int n_in,
                              void* d_out, int out_size) {
    const float* x    = (const float*)d_in[0];
    const float* bias = (const float*)d_in[1];
    float* out = (float*)d_out;

    {
        int total4 = Bdim * CS / 4;
        copy_in_kernel<<<(total4 + 255) / 256, 256>>>((const float4*)x, (float4*)out);
    }

    // D<=4: R=16, 256 threads (4 row groups). D>=5: R=32, 128 threads (2 row groups).
    launch_layer< 1,  1, 16, 4>(out, (const float*)d_in[2],  bias, 0);
    launch_layer< 3,  2, 16, 4>(out, (const float*)d_in[3],  bias, 1);
    launch_layer< 5,  3, 16, 4>(out, (const float*)d_in[4],  bias, 2);
    launch_layer< 7,  4, 16, 4>(out, (const float*)d_in[5],  bias, 3);
    launch_layer< 9,  5, 32, 2>(out, (const float*)d_in[6],  bias, 4);
    launch_layer<11,  6, 32, 2>(out, (const float*)d_in[7],  bias, 5);
    launch_layer<13,  7, 32, 2>(out, (const float*)d_in[8],  bias, 6);
    launch_layer<15,  8, 32, 2>(out, (const float*)d_in[9],  bias, 7);
    launch_layer<17,  9, 32, 2>(out, (const float*)d_in[10], bias, 8);
    launch_layer<19, 10, 32, 2>(out, (const float*)d_in[11], bias, 9);
    launch_layer<21, 11, 32, 2>(out, (const float*)d_in[12], bias, 10);
    launch_layer<23, 12, 32, 2>(out, (const float*)d_in[13], bias, 11);
}